// round 2
// baseline (speedup 1.0000x reference)
#include <cuda_runtime.h>
#include <cuda_bf16.h>
#include <math.h>

#define NPTS 16384
#define KNN  16
#define NCHUNK 8
#define CHSZ  (NPTS / NCHUNK)   // 2048

// ---------------- scratch (device globals, no allocations) ----------------
__device__ float4 d_pts4[NPTS];
__device__ float  d_ptsPad[NPTS * 16];
__device__ float  d_imfT[NPTS * 32];
__device__ float  d_T1[16 * 64];      // pconv1^T padded (K=16)
__device__ float  d_T2[64 * 128];     // pconv2^T
__device__ float  d_T3[32 * 64];      // conv1^T
__device__ float  d_T4[64 * 128];     // conv2^T
__device__ float  d_T5[128 * 256];    // psconv1^T
__device__ float  d_T6[256 * 128];    // psconv2^T
__device__ float  d_T7[416 * 32];     // final_w^T
__device__ float  d_t1[NPTS * 64];
__device__ float  d_cf[NPTS * 128];
__device__ float  d_t2[NPTS * 64];
__device__ float  d_g [NPTS * 128];
__device__ float  d_h1[NPTS * 256];
__device__ float  d_h [NPTS * 128];
__device__ float  d_pd[NPTS * NCHUNK * KNN];
__device__ int    d_pi[NPTS * NCHUNK * KNN];
__device__ int    d_knn[NPTS * KNN];

__device__ __forceinline__ float lrelu(float x) { return x > 0.f ? x : 0.01f * x; }

// ---------------- prep ----------------
__global__ void prep_kernel(const float* __restrict__ img, const float* __restrict__ cloud,
                            const float* __restrict__ c1w, const float* __restrict__ c2w,
                            const float* __restrict__ ps1w, const float* __restrict__ ps2w,
                            const float* __restrict__ pc1w, const float* __restrict__ pc2w,
                            const float* __restrict__ finw)
{
    const int stride = gridDim.x * blockDim.x;
    const int i0 = blockIdx.x * blockDim.x + threadIdx.x;
    for (int n = i0; n < NPTS; n += stride) {
        float x = cloud[n * 3 + 0], y = cloud[n * 3 + 1], z = cloud[n * 3 + 2];
        d_pts4[n] = make_float4(x, y, z, x * x + y * y + z * z);
        float* row = &d_ptsPad[n * 16];
        row[0] = x; row[1] = y; row[2] = z;
        #pragma unroll
        for (int k = 3; k < 16; k++) row[k] = 0.f;
    }
    for (int t = i0; t < NPTS * 32; t += stride)
        d_imfT[t] = img[(t & 31) * NPTS + (t >> 5)];
    for (int t = i0; t < 16 * 64; t += stride) {
        int k = t >> 6, j = t & 63;
        d_T1[t] = (k < 3) ? pc1w[j * 3 + k] : 0.f;
    }
    for (int t = i0; t < 64 * 128; t += stride) { int k = t >> 7, c = t & 127; d_T2[t] = pc2w[c * 64 + k]; }
    for (int t = i0; t < 32 * 64;  t += stride) { int k = t >> 6, j = t & 63;  d_T3[t] = c1w[j * 32 + k]; }
    for (int t = i0; t < 64 * 128; t += stride) { int k = t >> 7, c = t & 127; d_T4[t] = c2w[c * 64 + k]; }
    for (int t = i0; t < 128 * 256; t += stride) { int k = t >> 8, c = t & 255; d_T5[t] = ps1w[c * 128 + k]; }
    for (int t = i0; t < 256 * 128; t += stride) { int k = t >> 7, c = t & 127; d_T6[t] = ps2w[c * 256 + k]; }
    for (int t = i0; t < 416 * 32;  t += stride) { int c = t >> 5, j = t & 31;  d_T7[t] = finw[j * 416 + c]; }
}

// ---------------- KNN insertion helper (registers only, rare path) ----------------
__device__ __forceinline__ void insert16(float (&kd)[KNN], int (&ki)[KNN], float d, int idx)
{
    if (d < kd[KNN - 1]) {
        kd[KNN - 1] = d; ki[KNN - 1] = idx;
        #pragma unroll
        for (int t = KNN - 1; t > 0; --t) {
            if (kd[t] < kd[t - 1]) {
                float td = kd[t]; kd[t] = kd[t - 1]; kd[t - 1] = td;
                int   ti = ki[t]; ki[t] = ki[t - 1]; ki[t - 1] = ti;
            }
        }
    }
}

// ---------------- KNN partial: grid (64, 8), block 256 ----------------
// One query per lane; candidates staged in smem, broadcast warp-wide.
// Fast path: 8 distances + min-tree + 1 compare; slow path (rare): register insert.
__global__ void __launch_bounds__(256) knn_part_kernel()
{
    __shared__ float4 tile[CHSZ];
    const int q = blockIdx.x * 256 + threadIdx.x;
    const float4 pq = d_pts4[q];
    float kd[KNN]; int ki[KNN];
    #pragma unroll
    for (int t = 0; t < KNN; t++) { kd[t] = INFINITY; ki[t] = 0; }

    const int base = blockIdx.y * CHSZ;
    #pragma unroll
    for (int i = 0; i < CHSZ / 256; i++)
        tile[threadIdx.x + i * 256] = d_pts4[base + threadIdx.x + i * 256];
    __syncthreads();

    #pragma unroll 1
    for (int j = 0; j < CHSZ; j += 8) {
        const float4 c0 = tile[j + 0], c1 = tile[j + 1], c2 = tile[j + 2], c3 = tile[j + 3];
        const float4 c4 = tile[j + 4], c5 = tile[j + 5], c6 = tile[j + 6], c7 = tile[j + 7];
        const float d0 = fmaf(-2.f, fmaf(pq.x, c0.x, fmaf(pq.y, c0.y, pq.z * c0.z)), c0.w);
        const float d1 = fmaf(-2.f, fmaf(pq.x, c1.x, fmaf(pq.y, c1.y, pq.z * c1.z)), c1.w);
        const float d2 = fmaf(-2.f, fmaf(pq.x, c2.x, fmaf(pq.y, c2.y, pq.z * c2.z)), c2.w);
        const float d3 = fmaf(-2.f, fmaf(pq.x, c3.x, fmaf(pq.y, c3.y, pq.z * c3.z)), c3.w);
        const float d4 = fmaf(-2.f, fmaf(pq.x, c4.x, fmaf(pq.y, c4.y, pq.z * c4.z)), c4.w);
        const float d5 = fmaf(-2.f, fmaf(pq.x, c5.x, fmaf(pq.y, c5.y, pq.z * c5.z)), c5.w);
        const float d6 = fmaf(-2.f, fmaf(pq.x, c6.x, fmaf(pq.y, c6.y, pq.z * c6.z)), c6.w);
        const float d7 = fmaf(-2.f, fmaf(pq.x, c7.x, fmaf(pq.y, c7.y, pq.z * c7.z)), c7.w);
        const float m01 = fminf(d0, d1), m23 = fminf(d2, d3);
        const float m45 = fminf(d4, d5), m67 = fminf(d6, d7);
        const float mall = fminf(fminf(m01, m23), fminf(m45, m67));
        if (mall < kd[KNN - 1]) {
            insert16(kd, ki, d0, base + j + 0);
            insert16(kd, ki, d1, base + j + 1);
            insert16(kd, ki, d2, base + j + 2);
            insert16(kd, ki, d3, base + j + 3);
            insert16(kd, ki, d4, base + j + 4);
            insert16(kd, ki, d5, base + j + 5);
            insert16(kd, ki, d6, base + j + 6);
            insert16(kd, ki, d7, base + j + 7);
        }
    }
    const int off = (q * NCHUNK + blockIdx.y) * KNN;
    #pragma unroll
    for (int t = 0; t < KNN; t++) { d_pd[off + t] = kd[t]; d_pi[off + t] = ki[t]; }
}

// ---------------- KNN merge: warp per query, shfl argmin over 128 partials ----------------
__global__ void __launch_bounds__(256) knn_merge_kernel()
{
    const int w = threadIdx.x >> 5, lane = threadIdx.x & 31;
    const int q = blockIdx.x * 8 + w;

    const float4 dv = *(const float4*)&d_pd[q * (NCHUNK * KNN) + lane * 4];
    const int4   iv = *(const int4*)  &d_pi[q * (NCHUNK * KNN) + lane * 4];
    float e0 = dv.x, e1 = dv.y, e2 = dv.z, e3 = dv.w;

    #pragma unroll 1
    for (int r = 0; r < KNN; r++) {
        // local argmin over 4 regs
        float v = e0; int slot = 0;
        if (e1 < v) { v = e1; slot = 1; }
        if (e2 < v) { v = e2; slot = 2; }
        if (e3 < v) { v = e3; slot = 3; }
        // warp argmin (all lanes converge)
        float bv = v; int bl = lane;
        #pragma unroll
        for (int s = 16; s > 0; s >>= 1) {
            float ov = __shfl_xor_sync(0xffffffffu, bv, s);
            int   ol = __shfl_xor_sync(0xffffffffu, bl, s);
            if (ov < bv || (ov == bv && ol < bl)) { bv = ov; bl = ol; }
        }
        if (lane == bl) {
            int widx = (slot == 0) ? iv.x : (slot == 1) ? iv.y : (slot == 2) ? iv.z : iv.w;
            d_knn[q * KNN + r] = widx;
            if (slot == 0) e0 = INFINITY;
            else if (slot == 1) e1 = INFINITY;
            else if (slot == 2) e2 = INFINITY;
            else e3 = INFINITY;
        }
    }
}

// ---------------- generic fp32 GEMM: C = act(A[M,K] @ Bt[K,Nc] + bias) ----------------
__global__ void __launch_bounds__(256) gemm_kernel(const float* __restrict__ A,
                                                   const float* __restrict__ Bt,
                                                   const float* __restrict__ bias,
                                                   float* __restrict__ C,
                                                   int K, int Nc, int act)
{
    __shared__ float As[16][68];
    __shared__ float Bs[16][64];
    const int tid  = threadIdx.x;
    const int tcol = tid & 15, trow = tid >> 4;
    const int m0 = blockIdx.y * 64, n0 = blockIdx.x * 64;
    const int lmA = tid >> 2, lkA = (tid & 3) << 2;
    const int lkB = tid >> 4, lnB = (tid & 15) << 2;

    float acc[4][4];
    #pragma unroll
    for (int i = 0; i < 4; i++)
        #pragma unroll
        for (int j = 0; j < 4; j++) acc[i][j] = 0.f;

    for (int k0 = 0; k0 < K; k0 += 16) {
        float4 a = *(const float4*)&A[(m0 + lmA) * K + k0 + lkA];
        As[lkA + 0][lmA] = a.x; As[lkA + 1][lmA] = a.y;
        As[lkA + 2][lmA] = a.z; As[lkA + 3][lmA] = a.w;
        *(float4*)&Bs[lkB][lnB] = *(const float4*)&Bt[(k0 + lkB) * Nc + n0 + lnB];
        __syncthreads();
        #pragma unroll
        for (int k = 0; k < 16; k++) {
            float4 av = *(const float4*)&As[k][trow << 2];
            float4 bv = *(const float4*)&Bs[k][tcol << 2];
            float ar[4] = {av.x, av.y, av.z, av.w};
            float br[4] = {bv.x, bv.y, bv.z, bv.w};
            #pragma unroll
            for (int i = 0; i < 4; i++)
                #pragma unroll
                for (int j = 0; j < 4; j++)
                    acc[i][j] = fmaf(ar[i], br[j], acc[i][j]);
        }
        __syncthreads();
    }

    float4 bb = *(const float4*)&bias[n0 + (tcol << 2)];
    const float bbr[4] = {bb.x, bb.y, bb.z, bb.w};
    #pragma unroll
    for (int i = 0; i < 4; i++) {
        const int m = m0 + (trow << 2) + i;
        float4 r;
        float v0 = acc[i][0] + bbr[0], v1 = acc[i][1] + bbr[1];
        float v2 = acc[i][2] + bbr[2], v3 = acc[i][3] + bbr[3];
        if (act) { v0 = lrelu(v0); v1 = lrelu(v1); v2 = lrelu(v2); v3 = lrelu(v3); }
        r.x = v0; r.y = v1; r.z = v2; r.w = v3;
        *(float4*)&C[m * Nc + n0 + (tcol << 2)] = r;
    }
}

// ---------------- final: softmax weights, weighted max-pool, concat, GEMV ----------------
__global__ void __launch_bounds__(256) final_kernel(const float* __restrict__ img,
                                                    const float* __restrict__ fb,
                                                    float* __restrict__ out)
{
    __shared__ float swgt[8][KNN];
    __shared__ int   sidx[8][KNN];
    __shared__ float sfin[8][416];
    const int w = threadIdx.x >> 5, lane = threadIdx.x & 31;
    const int n = blockIdx.x * 8 + w;

    const float4 pq = d_pts4[n];
    float negd = -INFINITY; int myi = 0;
    if (lane < KNN) {
        myi = d_knn[n * KNN + lane];
        float4 pc = d_pts4[myi];
        float dx = pq.x - pc.x, dy = pq.y - pc.y, dz = pq.z - pc.z;
        negd = -sqrtf(fmaxf(dx * dx + dy * dy + dz * dz, 1e-12f));
    }
    float m = negd;
    #pragma unroll
    for (int s = 16; s > 0; s >>= 1) m = fmaxf(m, __shfl_xor_sync(0xffffffffu, m, s));
    float e = (lane < KNN) ? expf(negd - m) : 0.f;
    float ss = e;
    #pragma unroll
    for (int s = 16; s > 0; s >>= 1) ss += __shfl_xor_sync(0xffffffffu, ss, s);
    if (lane < KNN) { swgt[w][lane] = e / ss; sidx[w][lane] = myi; }
    __syncwarp();

    float4 sf = make_float4(-INFINITY, -INFINITY, -INFINITY, -INFINITY);
    float4 sp = make_float4(-INFINITY, -INFINITY, -INFINITY, -INFINITY);
    #pragma unroll
    for (int k = 0; k < KNN; k++) {
        const int ik = sidx[w][k];
        const float wk = swgt[w][k];
        const float4 gv = *(const float4*)&d_g[ik * 128 + (lane << 2)];
        const float4 hv = *(const float4*)&d_h[ik * 128 + (lane << 2)];
        sf.x = fmaxf(sf.x, gv.x * wk); sf.y = fmaxf(sf.y, gv.y * wk);
        sf.z = fmaxf(sf.z, gv.z * wk); sf.w = fmaxf(sf.w, gv.w * wk);
        sp.x = fmaxf(sp.x, hv.x * wk); sp.y = fmaxf(sp.y, hv.y * wk);
        sp.z = fmaxf(sp.z, hv.z * wk); sp.w = fmaxf(sp.w, hv.w * wk);
    }
    const int c4 = lane << 2;
    sfin[w][c4 + 0] = lrelu(sp.x); sfin[w][c4 + 1] = lrelu(sp.y);
    sfin[w][c4 + 2] = lrelu(sp.z); sfin[w][c4 + 3] = lrelu(sp.w);
    sfin[w][128 + lane] = lrelu(img[lane * NPTS + n]);
    sfin[w][160 + c4 + 0] = lrelu(sf.x); sfin[w][160 + c4 + 1] = lrelu(sf.y);
    sfin[w][160 + c4 + 2] = lrelu(sf.z); sfin[w][160 + c4 + 3] = lrelu(sf.w);
    const float4 cv = *(const float4*)&d_cf[n * 128 + c4];
    sfin[w][288 + c4 + 0] = lrelu(cv.x); sfin[w][288 + c4 + 1] = lrelu(cv.y);
    sfin[w][288 + c4 + 2] = lrelu(cv.z); sfin[w][288 + c4 + 3] = lrelu(cv.w);
    __syncwarp();

    float acc = fb[lane];
    #pragma unroll 8
    for (int c = 0; c < 416; c++)
        acc = fmaf(sfin[w][c], d_T7[c * 32 + lane], acc);
    out[lane * NPTS + n] = acc;
}

// ---------------- launch ----------------
extern "C" void kernel_launch(void* const* d_in, const int* in_sizes, int n_in,
                              void* d_out, int out_size)
{
    const float* img   = (const float*)d_in[0];
    const float* cloud = (const float*)d_in[1];
    const float* c1w  = (const float*)d_in[2];  const float* c1b  = (const float*)d_in[3];
    const float* c2w  = (const float*)d_in[4];  const float* c2b  = (const float*)d_in[5];
    const float* ps1w = (const float*)d_in[6];  const float* ps1b = (const float*)d_in[7];
    const float* ps2w = (const float*)d_in[8];  const float* ps2b = (const float*)d_in[9];
    const float* pc1w = (const float*)d_in[10]; const float* pc1b = (const float*)d_in[11];
    const float* pc2w = (const float*)d_in[12]; const float* pc2b = (const float*)d_in[13];
    const float* finw = (const float*)d_in[14]; const float* finb = (const float*)d_in[15];
    float* out = (float*)d_out;

    void *pPtsPad, *pT1, *pT2, *pT3, *pT4, *pT5, *pT6;
    void *pt1, *pcf, *pimfT, *pt2, *pg, *ph1, *ph;
    cudaGetSymbolAddress(&pPtsPad, d_ptsPad);
    cudaGetSymbolAddress(&pT1, d_T1); cudaGetSymbolAddress(&pT2, d_T2);
    cudaGetSymbolAddress(&pT3, d_T3); cudaGetSymbolAddress(&pT4, d_T4);
    cudaGetSymbolAddress(&pT5, d_T5); cudaGetSymbolAddress(&pT6, d_T6);
    cudaGetSymbolAddress(&pt1, d_t1); cudaGetSymbolAddress(&pcf, d_cf);
    cudaGetSymbolAddress(&pimfT, d_imfT); cudaGetSymbolAddress(&pt2, d_t2);
    cudaGetSymbolAddress(&pg, d_g); cudaGetSymbolAddress(&ph1, d_h1);
    cudaGetSymbolAddress(&ph, d_h);

    // launch 0
    prep_kernel<<<256, 256>>>(img, cloud, c1w, c2w, ps1w, ps2w, pc1w, pc2w, finw);
    // launches 1-4: KNN-independent GEMMs first (puts knn_part at ncu -s 5 slot)
    gemm_kernel<<<dim3(1, NPTS / 64), 256>>>((const float*)pPtsPad, (const float*)pT1, pc1b, (float*)pt1, 16, 64, 1);
    gemm_kernel<<<dim3(2, NPTS / 64), 256>>>((const float*)pt1, (const float*)pT2, pc2b, (float*)pcf, 64, 128, 0);
    gemm_kernel<<<dim3(1, NPTS / 64), 256>>>((const float*)pimfT, (const float*)pT3, c1b, (float*)pt2, 32, 64, 1);
    gemm_kernel<<<dim3(2, NPTS / 64), 256>>>((const float*)pt2, (const float*)pT4, c2b, (float*)pg, 64, 128, 0);
    // launch 5: the hotspot
    knn_part_kernel<<<dim3(NPTS / 256, NCHUNK), 256>>>();
    // launches 6-7
    gemm_kernel<<<dim3(4, NPTS / 64), 256>>>((const float*)pcf, (const float*)pT5, ps1b, (float*)ph1, 128, 256, 1);
    gemm_kernel<<<dim3(2, NPTS / 64), 256>>>((const float*)ph1, (const float*)pT6, ps2b, (float*)ph, 256, 128, 0);
    // launch 8
    knn_merge_kernel<<<NPTS / 8, 256>>>();
    // launch 9
    final_kernel<<<NPTS / 8, 256>>>(img, finb, out);
}

// round 4
// speedup vs baseline: 5.0429x; 5.0429x over previous
#include <cuda_runtime.h>
#include <cuda_bf16.h>
#include <math.h>

#define NPTS 16384
#define KNN  16
#define G    16
#define GC   (G * G * G)     // 4096 cells
#define HCELL (1.0f / G)

// ---------------- scratch (device globals, no allocations) ----------------
__device__ float4 d_pts4[NPTS];
__device__ float  d_ptsPad[NPTS * 16];
__device__ float  d_imfT[NPTS * 32];
__device__ float  d_T1[16 * 64];
__device__ float  d_T2[64 * 128];
__device__ float  d_T3[32 * 64];
__device__ float  d_T4[64 * 128];
__device__ float  d_T5[128 * 256];
__device__ float  d_T6[256 * 128];
__device__ float  d_T7[416 * 32];
__device__ float  d_t1[NPTS * 64];
__device__ float  d_cf[NPTS * 128];
__device__ float  d_t2[NPTS * 64];
__device__ float  d_g [NPTS * 128];
__device__ float  d_h1[NPTS * 256];
__device__ float  d_h [NPTS * 128];
__device__ int    d_knn[NPTS * KNN];
// grid structures
__device__ int    d_cellCnt[GC];
__device__ int    d_cellCur[GC];
__device__ int    d_cellStart[GC + 1];
__device__ int    d_ptCell[NPTS];
__device__ float4 d_spts[NPTS];
__device__ int    d_sidx[NPTS];

__device__ __forceinline__ float lrelu(float x) { return x > 0.f ? x : 0.01f * x; }

// ---------------- prep ----------------
__global__ void prep_kernel(const float* __restrict__ img, const float* __restrict__ cloud,
                            const float* __restrict__ c1w, const float* __restrict__ c2w,
                            const float* __restrict__ ps1w, const float* __restrict__ ps2w,
                            const float* __restrict__ pc1w, const float* __restrict__ pc2w,
                            const float* __restrict__ finw)
{
    const int stride = gridDim.x * blockDim.x;
    const int i0 = blockIdx.x * blockDim.x + threadIdx.x;
    for (int n = i0; n < NPTS; n += stride) {
        float x = cloud[n * 3 + 0], y = cloud[n * 3 + 1], z = cloud[n * 3 + 2];
        d_pts4[n] = make_float4(x, y, z, x * x + y * y + z * z);
        float* row = &d_ptsPad[n * 16];
        row[0] = x; row[1] = y; row[2] = z;
        #pragma unroll
        for (int k = 3; k < 16; k++) row[k] = 0.f;
    }
    for (int t = i0; t < NPTS * 32; t += stride)
        d_imfT[t] = img[(t & 31) * NPTS + (t >> 5)];
    for (int t = i0; t < 16 * 64; t += stride) {
        int k = t >> 6, j = t & 63;
        d_T1[t] = (k < 3) ? pc1w[j * 3 + k] : 0.f;
    }
    for (int t = i0; t < 64 * 128; t += stride) { int k = t >> 7, c = t & 127; d_T2[t] = pc2w[c * 64 + k]; }
    for (int t = i0; t < 32 * 64;  t += stride) { int k = t >> 6, j = t & 63;  d_T3[t] = c1w[j * 32 + k]; }
    for (int t = i0; t < 64 * 128; t += stride) { int k = t >> 7, c = t & 127; d_T4[t] = c2w[c * 64 + k]; }
    for (int t = i0; t < 128 * 256; t += stride) { int k = t >> 8, c = t & 255; d_T5[t] = ps1w[c * 128 + k]; }
    for (int t = i0; t < 256 * 128; t += stride) { int k = t >> 7, c = t & 127; d_T6[t] = ps2w[c * 256 + k]; }
    for (int t = i0; t < 416 * 32;  t += stride) { int c = t >> 5, j = t & 31;  d_T7[t] = finw[j * 416 + c]; }
}

// ---------------- grid build ----------------
__global__ void hist_kernel(const float* __restrict__ cloud)
{
    const int n = blockIdx.x * blockDim.x + threadIdx.x;
    if (n >= NPTS) return;
    float x = cloud[n * 3 + 0], y = cloud[n * 3 + 1], z = cloud[n * 3 + 2];
    int cx = min(G - 1, max(0, (int)(x * G)));
    int cy = min(G - 1, max(0, (int)(y * G)));
    int cz = min(G - 1, max(0, (int)(z * G)));
    int c = (cz * G + cy) * G + cx;
    d_ptCell[n] = c;
    atomicAdd(&d_cellCnt[c], 1);
}

__global__ void scan_kernel()   // one block, 1024 threads, 4096 cells
{
    __shared__ int ssum[1024];
    const int t = threadIdx.x;
    int c0 = d_cellCnt[4 * t + 0], c1 = d_cellCnt[4 * t + 1];
    int c2 = d_cellCnt[4 * t + 2], c3 = d_cellCnt[4 * t + 3];
    int s = c0 + c1 + c2 + c3;
    ssum[t] = s;
    __syncthreads();
    for (int off = 1; off < 1024; off <<= 1) {
        int v = (t >= off) ? ssum[t - off] : 0;
        __syncthreads();
        ssum[t] += v;
        __syncthreads();
    }
    int excl = ssum[t] - s;
    d_cellStart[4 * t + 0] = excl;
    d_cellStart[4 * t + 1] = excl + c0;
    d_cellStart[4 * t + 2] = excl + c0 + c1;
    d_cellStart[4 * t + 3] = excl + c0 + c1 + c2;
    if (t == 1023) d_cellStart[GC] = ssum[t];
}

__global__ void scatter_kernel()
{
    const int n = blockIdx.x * blockDim.x + threadIdx.x;
    if (n >= NPTS) return;
    const int c = d_ptCell[n];
    const int pos = d_cellStart[c] + atomicAdd(&d_cellCur[c], 1);
    d_spts[pos] = d_pts4[n];
    d_sidx[pos] = n;
}

// ---------------- KNN via grid: thread per (sorted) query ----------------
__device__ __forceinline__ void scan_cell(int cell, float qx, float qy, float qz,
                                          float (&kd)[KNN], int (&ki)[KNN])
{
    const int st = d_cellStart[cell], en = d_cellStart[cell + 1];
    for (int p = st; p < en; p++) {
        const float4 pc = d_spts[p];
        const float dx = qx - pc.x, dy = qy - pc.y, dz = qz - pc.z;
        const float d = fmaf(dx, dx, fmaf(dy, dy, dz * dz));
        if (d < kd[KNN - 1]) {
            kd[KNN - 1] = d; ki[KNN - 1] = p;
            #pragma unroll
            for (int t = KNN - 1; t > 0; --t) {
                if (kd[t] < kd[t - 1]) {
                    float td = kd[t]; kd[t] = kd[t - 1]; kd[t - 1] = td;
                    int   ti = ki[t]; ki[t] = ki[t - 1]; ki[t - 1] = ti;
                }
            }
        }
    }
}

__global__ void __launch_bounds__(256) knn_grid_kernel()
{
    const int s = blockIdx.x * 256 + threadIdx.x;
    const float4 pq = d_spts[s];
    const int cx = min(G - 1, max(0, (int)(pq.x * G)));
    const int cy = min(G - 1, max(0, (int)(pq.y * G)));
    const int cz = min(G - 1, max(0, (int)(pq.z * G)));

    float kd[KNN]; int ki[KNN];
    #pragma unroll
    for (int t = 0; t < KNN; t++) { kd[t] = INFINITY; ki[t] = 0; }

    for (int m = 0; m < G; m++) {
        const int x0 = max(cx - m, 0), x1 = min(cx + m, G - 1);
        const int y0 = max(cy - m, 0), y1 = min(cy + m, G - 1);
        const int z0 = max(cz - m, 0), z1 = min(cz + m, G - 1);
        for (int z = z0; z <= z1; z++) {
            const bool zs = (z == cz - m) || (z == cz + m);
            for (int y = y0; y <= y1; y++) {
                const bool edge = zs || (y == cy - m) || (y == cy + m);
                if (edge) {
                    const int rowc = (z * G + y) * G;
                    for (int x = x0; x <= x1; x++)
                        scan_cell(rowc + x, pq.x, pq.y, pq.z, kd, ki);
                } else {
                    if (cx - m >= 0) scan_cell((z * G + y) * G + cx - m, pq.x, pq.y, pq.z, kd, ki);
                    if (cx + m <= G - 1) scan_cell((z * G + y) * G + cx + m, pq.x, pq.y, pq.z, kd, ki);
                }
            }
        }
        const float bound = (float)m * HCELL;
        if (kd[KNN - 1] < bound * bound) break;   // all unvisited points are >= m*h away
    }

    const int orig = d_sidx[s];
    #pragma unroll
    for (int t = 0; t < KNN; t++)
        d_knn[orig * KNN + t] = d_sidx[ki[t]];
}

// ---------------- generic fp32 GEMM: C = act(A[M,K] @ Bt[K,Nc] + bias) ----------------
__global__ void __launch_bounds__(256) gemm_kernel(const float* __restrict__ A,
                                                   const float* __restrict__ Bt,
                                                   const float* __restrict__ bias,
                                                   float* __restrict__ C,
                                                   int K, int Nc, int act)
{
    __shared__ float As[16][68];
    __shared__ float Bs[16][64];
    const int tid  = threadIdx.x;
    const int tcol = tid & 15, trow = tid >> 4;
    const int m0 = blockIdx.y * 64, n0 = blockIdx.x * 64;
    const int lmA = tid >> 2, lkA = (tid & 3) << 2;
    const int lkB = tid >> 4, lnB = (tid & 15) << 2;

    float acc[4][4];
    #pragma unroll
    for (int i = 0; i < 4; i++)
        #pragma unroll
        for (int j = 0; j < 4; j++) acc[i][j] = 0.f;

    for (int k0 = 0; k0 < K; k0 += 16) {
        float4 a = *(const float4*)&A[(m0 + lmA) * K + k0 + lkA];
        As[lkA + 0][lmA] = a.x; As[lkA + 1][lmA] = a.y;
        As[lkA + 2][lmA] = a.z; As[lkA + 3][lmA] = a.w;
        *(float4*)&Bs[lkB][lnB] = *(const float4*)&Bt[(k0 + lkB) * Nc + n0 + lnB];
        __syncthreads();
        #pragma unroll
        for (int k = 0; k < 16; k++) {
            float4 av = *(const float4*)&As[k][trow << 2];
            float4 bv = *(const float4*)&Bs[k][tcol << 2];
            float ar[4] = {av.x, av.y, av.z, av.w};
            float br[4] = {bv.x, bv.y, bv.z, bv.w};
            #pragma unroll
            for (int i = 0; i < 4; i++)
                #pragma unroll
                for (int j = 0; j < 4; j++)
                    acc[i][j] = fmaf(ar[i], br[j], acc[i][j]);
        }
        __syncthreads();
    }

    float4 bb = *(const float4*)&bias[n0 + (tcol << 2)];
    const float bbr[4] = {bb.x, bb.y, bb.z, bb.w};
    #pragma unroll
    for (int i = 0; i < 4; i++) {
        const int m = m0 + (trow << 2) + i;
        float4 r;
        float v0 = acc[i][0] + bbr[0], v1 = acc[i][1] + bbr[1];
        float v2 = acc[i][2] + bbr[2], v3 = acc[i][3] + bbr[3];
        if (act) { v0 = lrelu(v0); v1 = lrelu(v1); v2 = lrelu(v2); v3 = lrelu(v3); }
        r.x = v0; r.y = v1; r.z = v2; r.w = v3;
        *(float4*)&C[m * Nc + n0 + (tcol << 2)] = r;
    }
}

// ---------------- final: softmax weights, weighted max-pool, concat, GEMV ----------------
__global__ void __launch_bounds__(256) final_kernel(const float* __restrict__ img,
                                                    const float* __restrict__ fb,
                                                    float* __restrict__ out)
{
    __shared__ float swgt[8][KNN];
    __shared__ int   sidx[8][KNN];
    __shared__ float sfin[8][416];
    const int w = threadIdx.x >> 5, lane = threadIdx.x & 31;
    const int n = blockIdx.x * 8 + w;

    const float4 pq = d_pts4[n];
    float negd = -INFINITY; int myi = 0;
    if (lane < KNN) {
        myi = d_knn[n * KNN + lane];
        float4 pc = d_pts4[myi];
        float dx = pq.x - pc.x, dy = pq.y - pc.y, dz = pq.z - pc.z;
        negd = -sqrtf(fmaxf(dx * dx + dy * dy + dz * dz, 1e-12f));
    }
    float m = negd;
    #pragma unroll
    for (int s = 16; s > 0; s >>= 1) m = fmaxf(m, __shfl_xor_sync(0xffffffffu, m, s));
    float e = (lane < KNN) ? expf(negd - m) : 0.f;
    float ss = e;
    #pragma unroll
    for (int s = 16; s > 0; s >>= 1) ss += __shfl_xor_sync(0xffffffffu, ss, s);
    if (lane < KNN) { swgt[w][lane] = e / ss; sidx[w][lane] = myi; }
    __syncwarp();

    float4 sf = make_float4(-INFINITY, -INFINITY, -INFINITY, -INFINITY);
    float4 sp = make_float4(-INFINITY, -INFINITY, -INFINITY, -INFINITY);
    #pragma unroll
    for (int k = 0; k < KNN; k++) {
        const int ik = sidx[w][k];
        const float wk = swgt[w][k];
        const float4 gv = *(const float4*)&d_g[ik * 128 + (lane << 2)];
        const float4 hv = *(const float4*)&d_h[ik * 128 + (lane << 2)];
        sf.x = fmaxf(sf.x, gv.x * wk); sf.y = fmaxf(sf.y, gv.y * wk);
        sf.z = fmaxf(sf.z, gv.z * wk); sf.w = fmaxf(sf.w, gv.w * wk);
        sp.x = fmaxf(sp.x, hv.x * wk); sp.y = fmaxf(sp.y, hv.y * wk);
        sp.z = fmaxf(sp.z, hv.z * wk); sp.w = fmaxf(sp.w, hv.w * wk);
    }
    const int c4 = lane << 2;
    sfin[w][c4 + 0] = lrelu(sp.x); sfin[w][c4 + 1] = lrelu(sp.y);
    sfin[w][c4 + 2] = lrelu(sp.z); sfin[w][c4 + 3] = lrelu(sp.w);
    sfin[w][128 + lane] = lrelu(img[lane * NPTS + n]);
    sfin[w][160 + c4 + 0] = lrelu(sf.x); sfin[w][160 + c4 + 1] = lrelu(sf.y);
    sfin[w][160 + c4 + 2] = lrelu(sf.z); sfin[w][160 + c4 + 3] = lrelu(sf.w);
    const float4 cv = *(const float4*)&d_cf[n * 128 + c4];
    sfin[w][288 + c4 + 0] = lrelu(cv.x); sfin[w][288 + c4 + 1] = lrelu(cv.y);
    sfin[w][288 + c4 + 2] = lrelu(cv.z); sfin[w][288 + c4 + 3] = lrelu(cv.w);
    __syncwarp();

    float acc = fb[lane];
    #pragma unroll 8
    for (int c = 0; c < 416; c++)
        acc = fmaf(sfin[w][c], d_T7[c * 32 + lane], acc);
    out[lane * NPTS + n] = acc;
}

// ---------------- launch ----------------
extern "C" void kernel_launch(void* const* d_in, const int* in_sizes, int n_in,
                              void* d_out, int out_size)
{
    const float* img   = (const float*)d_in[0];
    const float* cloud = (const float*)d_in[1];
    const float* c1w  = (const float*)d_in[2];  const float* c1b  = (const float*)d_in[3];
    const float* c2w  = (const float*)d_in[4];  const float* c2b  = (const float*)d_in[5];
    const float* ps1w = (const float*)d_in[6];  const float* ps1b = (const float*)d_in[7];
    const float* ps2w = (const float*)d_in[8];  const float* ps2b = (const float*)d_in[9];
    const float* pc1w = (const float*)d_in[10]; const float* pc1b = (const float*)d_in[11];
    const float* pc2w = (const float*)d_in[12]; const float* pc2b = (const float*)d_in[13];
    const float* finw = (const float*)d_in[14]; const float* finb = (const float*)d_in[15];
    float* out = (float*)d_out;

    void *pPtsPad, *pT1, *pT2, *pT3, *pT4, *pT5, *pT6;
    void *pt1, *pcf, *pimfT, *pt2, *pg, *ph1, *ph, *pCnt, *pCur;
    cudaGetSymbolAddress(&pPtsPad, d_ptsPad);
    cudaGetSymbolAddress(&pT1, d_T1); cudaGetSymbolAddress(&pT2, d_T2);
    cudaGetSymbolAddress(&pT3, d_T3); cudaGetSymbolAddress(&pT4, d_T4);
    cudaGetSymbolAddress(&pT5, d_T5); cudaGetSymbolAddress(&pT6, d_T6);
    cudaGetSymbolAddress(&pt1, d_t1); cudaGetSymbolAddress(&pcf, d_cf);
    cudaGetSymbolAddress(&pimfT, d_imfT); cudaGetSymbolAddress(&pt2, d_t2);
    cudaGetSymbolAddress(&pg, d_g); cudaGetSymbolAddress(&ph1, d_h1);
    cudaGetSymbolAddress(&ph, d_h);
    cudaGetSymbolAddress(&pCnt, d_cellCnt); cudaGetSymbolAddress(&pCur, d_cellCur);

    cudaMemsetAsync(pCnt, 0, GC * sizeof(int));
    cudaMemsetAsync(pCur, 0, GC * sizeof(int));

    prep_kernel<<<256, 256>>>(img, cloud, c1w, c2w, ps1w, ps2w, pc1w, pc2w, finw);
    hist_kernel<<<NPTS / 256, 256>>>(cloud);
    scan_kernel<<<1, 1024>>>();
    scatter_kernel<<<NPTS / 256, 256>>>();
    knn_grid_kernel<<<NPTS / 256, 256>>>();

    // point MLP: pts(16 padded) -> 64 (lrelu) -> 128
    gemm_kernel<<<dim3(1, NPTS / 64), 256>>>((const float*)pPtsPad, (const float*)pT1, pc1b, (float*)pt1, 16, 64, 1);
    gemm_kernel<<<dim3(2, NPTS / 64), 256>>>((const float*)pt1, (const float*)pT2, pc2b, (float*)pcf, 64, 128, 0);
    // img MLP: imf(32) -> 64 (lrelu) -> 128
    gemm_kernel<<<dim3(1, NPTS / 64), 256>>>((const float*)pimfT, (const float*)pT3, c1b, (float*)pt2, 32, 64, 1);
    gemm_kernel<<<dim3(2, NPTS / 64), 256>>>((const float*)pt2, (const float*)pT4, c2b, (float*)pg, 64, 128, 0);
    // ps MLP: cf(128) -> 256 (lrelu) -> 128
    gemm_kernel<<<dim3(4, NPTS / 64), 256>>>((const float*)pcf, (const float*)pT5, ps1b, (float*)ph1, 128, 256, 1);
    gemm_kernel<<<dim3(2, NPTS / 64), 256>>>((const float*)ph1, (const float*)pT6, ps2b, (float*)ph, 256, 128, 0);

    final_kernel<<<NPTS / 8, 256>>>(img, finb, out);
}